// round 13
// baseline (speedup 1.0000x reference)
#include <cuda_runtime.h>
#include <cuda_fp16.h>

// ---------------------------------------------------------------------------
// GAT 2-layer forward, sparse-aware.
// Round 13: csr made PERSISTENT (148 CTAs, 1/SM, row-loop) and launched first
// so one csr CTA is resident on every SM before gemm's 2 CTAs/SM arrive ->
// true co-residency on all SMs (R10/R12 overlap only used ~20 leftover SMs).
// ---------------------------------------------------------------------------

#define N_NODES 8192
#define F_IN    512
#define H1      128
#define KHEADS  2
#define HCAT    256
#define C_OUT   16
#define MAXDEG  256
#define LALPHA  0.2f
#define CSR_CTAS 148
#define CSR_WARPS (CSR_CTAS * 8)    // 1184

// ---- scratch (device globals; no allocation allowed) ----
__device__ int    g_deg[N_NODES];
__device__ int    g_nbr[N_NODES * MAXDEG];
__device__ __half g_Hall[N_NODES * HCAT];
__device__ float  g_f1s[KHEADS][N_NODES];
__device__ float  g_f1d[KHEADS][N_NODES];
__device__ float  g_h2[N_NODES * C_OUT];
__device__ float  g_f2s[N_NODES];
__device__ float  g_f2d[N_NODES];

// ---------------------------------------------------------------------------
// CSR build: persistent, one CTA per SM, warps loop over rows (stride 1184).
// uint4 x8 batches (MLP 8) + L2 prefetch. Reg cap 64 via launch_bounds(256,4)
// so a csr CTA co-resides with two gemm CTAs (49K + 14K < 64K regs).
// ---------------------------------------------------------------------------
__device__ __forceinline__ unsigned nib_ne0(unsigned w) {
    return (((__vcmpne4(w, 0u) & 0x01010101u) * 0x01020408u) >> 24) & 0xFu;
}

__global__ __launch_bounds__(256, 4) void build_csr(const void* adjv) {
    int gwarp = (blockIdx.x * blockDim.x + threadIdx.x) >> 5;
    int lane  = threadIdx.x & 31;

    const unsigned char* a8 = (const unsigned char*)adjv;
    bool byte_mode = ((a8[8193] | a8[3 * 8193] | a8[5 * 8193]) != 0);

    for (int row = gwarp; row < N_NODES; row += CSR_WARPS) {
        int cnt = 0;
        int* nbr = g_nbr + (size_t)row * MAXDEG;

        if (!byte_mode) {
            const uint4* p = (const uint4*)((const unsigned*)adjv + (size_t)row * N_NODES);
            #pragma unroll
            for (int j = 0; j < 16; j++)
                asm volatile("prefetch.global.L2 [%0];" :: "l"(p + j * 32 + lane));
            #pragma unroll 1
            for (int it = 0; it < 64; it += 8) {
                if (it + 16 < 64) {
                    #pragma unroll
                    for (int j = 0; j < 8; j++)
                        asm volatile("prefetch.global.L2 [%0];"
                                     :: "l"(p + (it + 16 + j) * 32 + lane));
                }
                uint4 v[8];
                #pragma unroll
                for (int j = 0; j < 8; j++) v[j] = p[(it + j) * 32 + lane];
                unsigned mask = 0;
                #pragma unroll
                for (int j = 0; j < 8; j++) {
                    mask |= (v[j].x != 0u ? 1u : 0u) << (j * 4);
                    mask |= (v[j].y != 0u ? 2u : 0u) << (j * 4);
                    mask |= (v[j].z != 0u ? 4u : 0u) << (j * 4);
                    mask |= (v[j].w != 0u ? 8u : 0u) << (j * 4);
                }
                int myc = __popc(mask);
                int scan = myc;
                #pragma unroll
                for (int o = 1; o < 32; o <<= 1) {
                    int t = __shfl_up_sync(0xFFFFFFFFu, scan, o);
                    if (lane >= o) scan += t;
                }
                int pos = cnt + scan - myc;
                while (mask) {
                    int b = __ffs(mask) - 1;
                    mask &= mask - 1;
                    int col = ((it + (b >> 2)) * 32 + lane) * 4 + (b & 3);
                    if (pos < MAXDEG) nbr[pos] = col;
                    pos++;
                }
                cnt += __shfl_sync(0xFFFFFFFFu, scan, 31);
            }
        } else {
            const uint4* p = (const uint4*)(a8 + (size_t)row * N_NODES);
            #pragma unroll 1
            for (int it = 0; it < 16; it += 4) {
                uint4 v[4];
                #pragma unroll
                for (int j = 0; j < 4; j++) v[j] = p[(it + j) * 32 + lane];
                #pragma unroll
                for (int j = 0; j < 4; j++) {
                    unsigned mask = nib_ne0(v[j].x) | (nib_ne0(v[j].y) << 4)
                                  | (nib_ne0(v[j].z) << 8) | (nib_ne0(v[j].w) << 12);
                    int myc = __popc(mask);
                    int scan = myc;
                    #pragma unroll
                    for (int o = 1; o < 32; o <<= 1) {
                        int t = __shfl_up_sync(0xFFFFFFFFu, scan, o);
                        if (lane >= o) scan += t;
                    }
                    int pos = cnt + scan - myc;
                    int colbase = ((it + j) * 32 + lane) * 16;
                    while (mask) {
                        int b = __ffs(mask) - 1;
                        mask &= mask - 1;
                        if (pos < MAXDEG) nbr[pos] = colbase + b;
                        pos++;
                    }
                    cnt += __shfl_sync(0xFFFFFFFFu, scan, 31);
                }
            }
        }
        if (lane == 0) g_deg[row] = (cnt < MAXDEG) ? cnt : MAXDEG;
    }
}

// ---------------------------------------------------------------------------
// GEMM1 on tensor cores (tf32 3-term split), double-buffered, fused f1 epilogue.
// ---------------------------------------------------------------------------
#define BM 64
#define BK 16

#define OFF_AHI 0
#define OFF_ALO 2560
#define OFF_BHI 5120
#define OFF_BLO 9472
#define OFF_SHS 13824
#define OFF_SHD 13888
#define SMEM_WORDS 13952

#define A_HI(b, r, c) sm[OFF_AHI + (b) * 1280 + (r) * 20 + (c)]
#define A_LO(b, r, c) sm[OFF_ALO + (b) * 1280 + (r) * 20 + (c)]
#define B_HI(b, k, n) sm[OFF_BHI + (b) * 2176 + (k) * 136 + (n)]
#define B_LO(b, k, n) sm[OFF_BLO + (b) * 2176 + (k) * 136 + (n)]

__device__ __forceinline__ void split_tf32(float v, unsigned& hi, unsigned& lo) {
    asm("cvt.rna.tf32.f32 %0, %1;" : "=r"(hi) : "f"(v));
    float r = v - __uint_as_float(hi);
    asm("cvt.rna.tf32.f32 %0, %1;" : "=r"(lo) : "f"(r));
}

#define MMA_TF32(c, a0, a1, a2, a3, b0, b1)                                     \
    asm volatile(                                                               \
        "mma.sync.aligned.m16n8k8.row.col.f32.tf32.tf32.f32 "                   \
        "{%0,%1,%2,%3},{%4,%5,%6,%7},{%8,%9},{%0,%1,%2,%3};"                    \
        : "+f"(c[0]), "+f"(c[1]), "+f"(c[2]), "+f"(c[3])                        \
        : "r"(a0), "r"(a1), "r"(a2), "r"(a3), "r"(b0), "r"(b1))

__global__ __launch_bounds__(256, 2) void gemm1_tc(const float* __restrict__ x,
                                                   const float* __restrict__ W1,
                                                   const float* __restrict__ a1s,
                                                   const float* __restrict__ a1d) {
    extern __shared__ unsigned sm[];
    float* sh_s = (float*)(sm + OFF_SHS);
    float* sh_d = (float*)(sm + OFF_SHD);

    const int head = blockIdx.x;
    const int row0 = blockIdx.y * BM;
    const int tid  = threadIdx.x;
    const int warp = tid >> 5;
    const int lane = tid & 31;
    const int warpM = warp >> 2;
    const int warpN = warp & 3;
    const float* Wh = W1 + (size_t)head * F_IN * H1;

    if (tid < BM) { sh_s[tid] = 0.0f; sh_d[tid] = 0.0f; }

    float acc[2][4][4];
    #pragma unroll
    for (int mt = 0; mt < 2; mt++)
        #pragma unroll
        for (int nt = 0; nt < 4; nt++)
            #pragma unroll
            for (int r = 0; r < 4; r++) acc[mt][nt][r] = 0.0f;

    const int aM  = tid >> 2;
    const int aK4 = (tid & 3) * 4;
    const int bK[2]  = { (0 * 256 + tid) >> 5,       (1 * 256 + tid) >> 5 };
    const int bN4[2] = { ((0 * 256 + tid) & 31) * 4, ((1 * 256 + tid) & 31) * 4 };

    float4 ax, bw[2];

    ax = *(const float4*)(x + (size_t)(row0 + aM) * F_IN + aK4);
    #pragma unroll
    for (int it = 0; it < 2; it++)
        bw[it] = *(const float4*)(Wh + (size_t)bK[it] * H1 + bN4[it]);
    {
        uint4 h4, l4;
        split_tf32(ax.x, h4.x, l4.x);
        split_tf32(ax.y, h4.y, l4.y);
        split_tf32(ax.z, h4.z, l4.z);
        split_tf32(ax.w, h4.w, l4.w);
        *(uint4*)&A_HI(0, aM, aK4) = h4;
        *(uint4*)&A_LO(0, aM, aK4) = l4;
        #pragma unroll
        for (int it = 0; it < 2; it++) {
            split_tf32(bw[it].x, h4.x, l4.x);
            split_tf32(bw[it].y, h4.y, l4.y);
            split_tf32(bw[it].z, h4.z, l4.z);
            split_tf32(bw[it].w, h4.w, l4.w);
            *(uint4*)&B_HI(0, bK[it], bN4[it]) = h4;
            *(uint4*)&B_LO(0, bK[it], bN4[it]) = l4;
        }
    }
    __syncthreads();

    const int NT = F_IN / BK;
    for (int i = 0; i < NT; i++) {
        const int cur = i & 1;
        const bool has_next = (i + 1 < NT);
        if (has_next) {
            const int kn = (i + 1) * BK;
            ax = *(const float4*)(x + (size_t)(row0 + aM) * F_IN + kn + aK4);
            #pragma unroll
            for (int it = 0; it < 2; it++)
                bw[it] = *(const float4*)(Wh + (size_t)(kn + bK[it]) * H1 + bN4[it]);
        }

        #pragma unroll
        for (int ks = 0; ks < 2; ks++) {
            const int kb = ks * 8;
            unsigned ah[2][4], al[2][4], bh[4][2], bl[4][2];
            const int ar = warpM * 32 + (lane >> 2);
            const int kc = kb + (lane & 3);
            #pragma unroll
            for (int mt = 0; mt < 2; mt++) {
                int r = ar + mt * 16;
                ah[mt][0] = A_HI(cur, r, kc);         ah[mt][1] = A_HI(cur, r + 8, kc);
                ah[mt][2] = A_HI(cur, r, kc + 4);     ah[mt][3] = A_HI(cur, r + 8, kc + 4);
                al[mt][0] = A_LO(cur, r, kc);         al[mt][1] = A_LO(cur, r + 8, kc);
                al[mt][2] = A_LO(cur, r, kc + 4);     al[mt][3] = A_LO(cur, r + 8, kc + 4);
            }
            const int bn = warpN * 32 + (lane >> 2);
            const int kr = kb + (lane & 3);
            #pragma unroll
            for (int nt = 0; nt < 4; nt++) {
                bh[nt][0] = B_HI(cur, kr, bn + nt * 8);
                bh[nt][1] = B_HI(cur, kr + 4, bn + nt * 8);
                bl[nt][0] = B_LO(cur, kr, bn + nt * 8);
                bl[nt][1] = B_LO(cur, kr + 4, bn + nt * 8);
            }
            #pragma unroll
            for (int mt = 0; mt < 2; mt++)
                #pragma unroll
                for (int nt = 0; nt < 4; nt++) {
                    MMA_TF32(acc[mt][nt], ah[mt][0], ah[mt][1], ah[mt][2], ah[mt][3],
                             bh[nt][0], bh[nt][1]);
                    MMA_TF32(acc[mt][nt], ah[mt][0], ah[mt][1], ah[mt][2], ah[mt][3],
                             bl[nt][0], bl[nt][1]);
                    MMA_TF32(acc[mt][nt], al[mt][0], al[mt][1], al[mt][2], al[mt][3],
                             bh[nt][0], bh[nt][1]);
                }
        }

        if (has_next) {
            const int nxt = cur ^ 1;
            uint4 h4, l4;
            split_tf32(ax.x, h4.x, l4.x);
            split_tf32(ax.y, h4.y, l4.y);
            split_tf32(ax.z, h4.z, l4.z);
            split_tf32(ax.w, h4.w, l4.w);
            *(uint4*)&A_HI(nxt, aM, aK4) = h4;
            *(uint4*)&A_LO(nxt, aM, aK4) = l4;
            #pragma unroll
            for (int it = 0; it < 2; it++) {
                split_tf32(bw[it].x, h4.x, l4.x);
                split_tf32(bw[it].y, h4.y, l4.y);
                split_tf32(bw[it].z, h4.z, l4.z);
                split_tf32(bw[it].w, h4.w, l4.w);
                *(uint4*)&B_HI(nxt, bK[it], bN4[it]) = h4;
                *(uint4*)&B_LO(nxt, bK[it], bN4[it]) = l4;
            }
            __syncthreads();
        }
    }

    float asv[4][2], adv[4][2];
    const int colb = warpN * 32;
    #pragma unroll
    for (int nt = 0; nt < 4; nt++) {
        int c = colb + nt * 8 + 2 * (lane & 3);
        asv[nt][0] = a1s[head * H1 + c];
        asv[nt][1] = a1s[head * H1 + c + 1];
        adv[nt][0] = a1d[head * H1 + c];
        adv[nt][1] = a1d[head * H1 + c + 1];
    }

    __syncthreads();
    #pragma unroll
    for (int mt = 0; mt < 2; mt++) {
        float s0 = 0.f, s1 = 0.f, d0 = 0.f, d1 = 0.f;
        #pragma unroll
        for (int nt = 0; nt < 4; nt++) {
            s0 += acc[mt][nt][0] * asv[nt][0] + acc[mt][nt][1] * asv[nt][1];
            s1 += acc[mt][nt][2] * asv[nt][0] + acc[mt][nt][3] * asv[nt][1];
            d0 += acc[mt][nt][0] * adv[nt][0] + acc[mt][nt][1] * adv[nt][1];
            d1 += acc[mt][nt][2] * adv[nt][0] + acc[mt][nt][3] * adv[nt][1];
        }
        #pragma unroll
        for (int o = 1; o <= 2; o <<= 1) {
            s0 += __shfl_xor_sync(0xFFFFFFFFu, s0, o);
            s1 += __shfl_xor_sync(0xFFFFFFFFu, s1, o);
            d0 += __shfl_xor_sync(0xFFFFFFFFu, d0, o);
            d1 += __shfl_xor_sync(0xFFFFFFFFu, d1, o);
        }
        int rl = warpM * 32 + mt * 16 + (lane >> 2);
        if ((lane & 3) == 0) {
            atomicAdd(&sh_s[rl], s0);     atomicAdd(&sh_d[rl], d0);
            atomicAdd(&sh_s[rl + 8], s1); atomicAdd(&sh_d[rl + 8], d1);
        }
        int gr0 = row0 + rl;
        #pragma unroll
        for (int nt = 0; nt < 4; nt++) {
            int c = head * H1 + colb + nt * 8 + 2 * (lane & 3);
            *(__half2*)&g_Hall[(size_t)gr0 * HCAT + c] =
                __floats2half2_rn(acc[mt][nt][0], acc[mt][nt][1]);
            *(__half2*)&g_Hall[(size_t)(gr0 + 8) * HCAT + c] =
                __floats2half2_rn(acc[mt][nt][2], acc[mt][nt][3]);
        }
    }
    __syncthreads();
    if (tid < BM) {
        g_f1s[head][row0 + tid] = sh_s[tid];
        g_f1d[head][row0 + tid] = sh_d[tid];
    }
}

// ---------------------------------------------------------------------------
// Layer-1 attention + aggregate (fp16 gathers) + relu, fused layer-2 GEMM.
// ---------------------------------------------------------------------------
__global__ __launch_bounds__(256) void attn1_fused(const float* __restrict__ W2,
                                                   const float* __restrict__ a2s,
                                                   const float* __restrict__ a2d) {
    const int n = blockIdx.x;
    __shared__ int    s_nbr[MAXDEG];
    __shared__ float  s_w[2][MAXDEG];
    __shared__ float  s_red[2][2];
    __shared__ float4 s_acc[3][64];
    __shared__ float  s_h1[HCAT];
    __shared__ float  s_p[16][17];
    const int tid = threadIdx.x;
    const int deg = g_deg[n];

    if (tid < deg) s_nbr[tid] = g_nbr[(size_t)n * MAXDEG + tid];
    __syncthreads();
    if (tid < deg) {
        int m = s_nbr[tid];
        #pragma unroll
        for (int k = 0; k < 2; k++) {
            float e = g_f1s[k][n] + g_f1d[k][m];
            s_w[k][tid] = (e > 0.0f) ? e : LALPHA * e;
        }
    }
    __syncthreads();
    {
        int w = tid >> 5, lane = tid & 31;
        if (w < 2) {
            float mx = -1e30f;
            for (int i = lane; i < deg; i += 32) mx = fmaxf(mx, s_w[w][i]);
            #pragma unroll
            for (int o = 16; o; o >>= 1) mx = fmaxf(mx, __shfl_xor_sync(0xFFFFFFFFu, mx, o));
            float sm = 0.0f;
            for (int i = lane; i < deg; i += 32) sm += __expf(s_w[w][i] - mx);
            #pragma unroll
            for (int o = 16; o; o >>= 1) sm += __shfl_xor_sync(0xFFFFFFFFu, sm, o);
            if (lane == 0) { s_red[w][0] = mx; s_red[w][1] = sm; }
        }
    }
    __syncthreads();
    if (tid < deg) {
        #pragma unroll
        for (int k = 0; k < 2; k++)
            s_w[k][tid] = __expf(s_w[k][tid] - s_red[k][0]) / s_red[k][1];
    }
    __syncthreads();

    const int g  = tid >> 6;
    const int c4 = tid & 63;
    const int k  = c4 >> 5;
    float4 acc = make_float4(0.f, 0.f, 0.f, 0.f);
    for (int i = g; i < deg; i += 4) {
        float w = s_w[k][i];
        uint2 raw = *(const uint2*)&g_Hall[(size_t)s_nbr[i] * HCAT + 4 * c4];
        float2 f01 = __half22float2(*(__half2*)&raw.x);
        float2 f23 = __half22float2(*(__half2*)&raw.y);
        acc.x = fmaf(w, f01.x, acc.x);
        acc.y = fmaf(w, f01.y, acc.y);
        acc.z = fmaf(w, f23.x, acc.z);
        acc.w = fmaf(w, f23.y, acc.w);
    }
    if (g) s_acc[g - 1][c4] = acc;
    __syncthreads();
    if (g == 0) {
        #pragma unroll
        for (int j = 0; j < 3; j++) {
            float4 v = s_acc[j][c4];
            acc.x += v.x; acc.y += v.y; acc.z += v.z; acc.w += v.w;
        }
        acc.x = fmaxf(acc.x, 0.f); acc.y = fmaxf(acc.y, 0.f);
        acc.z = fmaxf(acc.z, 0.f); acc.w = fmaxf(acc.w, 0.f);
        *(float4*)&s_h1[4 * c4] = acc;
    }
    __syncthreads();

    const int fg = tid >> 4;
    const int c  = tid & 15;
    float pa = 0.0f;
    #pragma unroll
    for (int j = 0; j < 16; j++) {
        int f = fg * 16 + j;
        pa = fmaf(s_h1[f], W2[f * C_OUT + c], pa);
    }
    s_p[fg][c] = pa;
    __syncthreads();
    if (tid < 16) {
        float h2c = 0.0f;
        #pragma unroll
        for (int j = 0; j < 16; j++) h2c += s_p[j][tid];
        g_h2[n * C_OUT + tid] = h2c;
        float vs = h2c * a2s[tid];
        float vd = h2c * a2d[tid];
        #pragma unroll
        for (int o = 8; o; o >>= 1) {
            vs += __shfl_xor_sync(0x0000FFFFu, vs, o, 16);
            vd += __shfl_xor_sync(0x0000FFFFu, vd, o, 16);
        }
        if (tid == 0) { g_f2s[n] = vs; g_f2d[n] = vd; }
    }
}

// ---------------------------------------------------------------------------
// Layer-2 attention: one warp per node, neighbor-per-lane.
// ---------------------------------------------------------------------------
__global__ __launch_bounds__(256) void attn2(float* __restrict__ out) {
    int wIn = threadIdx.x >> 5, lane = threadIdx.x & 31;
    int n = blockIdx.x * 8 + wIn;
    if (n >= N_NODES) return;
    int deg = g_deg[n];
    const int* nbr = g_nbr + (size_t)n * MAXDEG;
    float fsn = g_f2s[n];

    int   myn[4];
    float ev[4];
    int cnt = 0;
    float mx = -1e30f;
    for (int i = lane; i < deg; i += 32) {
        int m = nbr[i];
        float e = fsn + g_f2d[m];
        e = (e > 0.0f) ? e : LALPHA * e;
        if (cnt < 4) { myn[cnt] = m; ev[cnt] = e; cnt++; }
        mx = fmaxf(mx, e);
    }
    #pragma unroll
    for (int o = 16; o; o >>= 1) mx = fmaxf(mx, __shfl_xor_sync(0xFFFFFFFFu, mx, o));
    float sm = 0.0f;
    #pragma unroll
    for (int j = 0; j < 4; j++)
        if (j < cnt) { ev[j] = __expf(ev[j] - mx); sm += ev[j]; }
    #pragma unroll
    for (int o = 16; o; o >>= 1) sm += __shfl_xor_sync(0xFFFFFFFFu, sm, o);
    float inv = 1.0f / sm;

    float4 a0 = make_float4(0,0,0,0), a1 = make_float4(0,0,0,0);
    float4 a2 = make_float4(0,0,0,0), a3 = make_float4(0,0,0,0);
    #pragma unroll
    for (int j = 0; j < 4; j++) {
        if (j < cnt) {
            float w = ev[j];
            const float4* hp = (const float4*)&g_h2[(size_t)myn[j] * C_OUT];
            float4 v0 = hp[0], v1 = hp[1], v2 = hp[2], v3 = hp[3];
            a0.x = fmaf(w, v0.x, a0.x); a0.y = fmaf(w, v0.y, a0.y);
            a0.z = fmaf(w, v0.z, a0.z); a0.w = fmaf(w, v0.w, a0.w);
            a1.x = fmaf(w, v1.x, a1.x); a1.y = fmaf(w, v1.y, a1.y);
            a1.z = fmaf(w, v1.z, a1.z); a1.w = fmaf(w, v1.w, a1.w);
            a2.x = fmaf(w, v2.x, a2.x); a2.y = fmaf(w, v2.y, a2.y);
            a2.z = fmaf(w, v2.z, a2.z); a2.w = fmaf(w, v2.w, a2.w);
            a3.x = fmaf(w, v3.x, a3.x); a3.y = fmaf(w, v3.y, a3.y);
            a3.z = fmaf(w, v3.z, a3.z); a3.w = fmaf(w, v3.w, a3.w);
        }
    }
    #pragma unroll
    for (int o = 16; o; o >>= 1) {
        a0.x += __shfl_xor_sync(0xFFFFFFFFu, a0.x, o);
        a0.y += __shfl_xor_sync(0xFFFFFFFFu, a0.y, o);
        a0.z += __shfl_xor_sync(0xFFFFFFFFu, a0.z, o);
        a0.w += __shfl_xor_sync(0xFFFFFFFFu, a0.w, o);
        a1.x += __shfl_xor_sync(0xFFFFFFFFu, a1.x, o);
        a1.y += __shfl_xor_sync(0xFFFFFFFFu, a1.y, o);
        a1.z += __shfl_xor_sync(0xFFFFFFFFu, a1.z, o);
        a1.w += __shfl_xor_sync(0xFFFFFFFFu, a1.w, o);
        a2.x += __shfl_xor_sync(0xFFFFFFFFu, a2.x, o);
        a2.y += __shfl_xor_sync(0xFFFFFFFFu, a2.y, o);
        a2.z += __shfl_xor_sync(0xFFFFFFFFu, a2.z, o);
        a2.w += __shfl_xor_sync(0xFFFFFFFFu, a2.w, o);
        a3.x += __shfl_xor_sync(0xFFFFFFFFu, a3.x, o);
        a3.y += __shfl_xor_sync(0xFFFFFFFFu, a3.y, o);
        a3.z += __shfl_xor_sync(0xFFFFFFFFu, a3.z, o);
        a3.w += __shfl_xor_sync(0xFFFFFFFFu, a3.w, o);
    }
    if (lane == 0) {
        float4* op = (float4*)&out[(size_t)n * C_OUT];
        a0.x *= inv; a0.y *= inv; a0.z *= inv; a0.w *= inv;
        a1.x *= inv; a1.y *= inv; a1.z *= inv; a1.w *= inv;
        a2.x *= inv; a2.y *= inv; a2.z *= inv; a2.w *= inv;
        a3.x *= inv; a3.y *= inv; a3.z *= inv; a3.w *= inv;
        op[0] = a0; op[1] = a1; op[2] = a2; op[3] = a3;
    }
}

// ---------------------------------------------------------------------------
extern "C" void kernel_launch(void* const* d_in, const int* in_sizes, int n_in,
                              void* d_out, int out_size) {
    const float* x   = (const float*)d_in[0];
    const void*  adj = d_in[1];
    const float* W1  = (const float*)d_in[2];
    const float* a1s = (const float*)d_in[3];
    const float* a1d = (const float*)d_in[4];
    const float* W2  = (const float*)d_in[5];
    const float* a2s = (const float*)d_in[6];
    const float* a2d = (const float*)d_in[7];
    float* out = (float*)d_out;

    static cudaStream_t s_side = nullptr;
    static cudaEvent_t  s_fork = nullptr, s_join = nullptr;
    static bool s_attr_done = false;
    if (!s_side) {
        cudaStreamCreateWithFlags(&s_side, cudaStreamNonBlocking);
        cudaEventCreateWithFlags(&s_fork, cudaEventDisableTiming);
        cudaEventCreateWithFlags(&s_join, cudaEventDisableTiming);
    }
    if (!s_attr_done) {
        cudaFuncSetAttribute(gemm1_tc, cudaFuncAttributeMaxDynamicSharedMemorySize,
                             SMEM_WORDS * 4);
        s_attr_done = true;
    }

    // fork: persistent csr launched FIRST (1 CTA/SM on all SMs), gemm second
    // (2 CTAs/SM fill beside it). Both co-resident everywhere.
    cudaEventRecord(s_fork, 0);
    cudaStreamWaitEvent(s_side, s_fork, 0);

    build_csr<<<CSR_CTAS, 256>>>(adj);

    dim3 g1(KHEADS, N_NODES / BM);             // (2, 128) = 256 CTAs
    gemm1_tc<<<g1, 256, SMEM_WORDS * 4, s_side>>>(x, W1, a1s, a1d);

    cudaEventRecord(s_join, s_side);
    cudaStreamWaitEvent(0, s_join, 0);

    attn1_fused<<<N_NODES, 256>>>(W2, a2s, a2d);
    attn2<<<N_NODES / 8, 256>>>(out);
}

// round 14
// speedup vs baseline: 1.2867x; 1.2867x over previous
#include <cuda_runtime.h>
#include <cuda_fp16.h>

// ---------------------------------------------------------------------------
// GAT 2-layer forward, sparse-aware.
// Round 14: revert R13 (persistent csr regressed). R12 structure + gemm uses
// 2-term tf32 split (xh*Wh + xh*Wl; drop xl*Wh) -- legacy-mma path is
// MAC-throughput bound, so 2/3 MACs => ~2/3 time. Error ~2e-4 rel (gate 1e-3).
// ---------------------------------------------------------------------------

#define N_NODES 8192
#define F_IN    512
#define H1      128
#define KHEADS  2
#define HCAT    256
#define C_OUT   16
#define MAXDEG  256
#define LALPHA  0.2f

// ---- scratch (device globals; no allocation allowed) ----
__device__ int    g_deg[N_NODES];
__device__ int    g_nbr[N_NODES * MAXDEG];
__device__ __half g_Hall[N_NODES * HCAT];
__device__ float  g_f1s[KHEADS][N_NODES];
__device__ float  g_f1d[KHEADS][N_NODES];
__device__ float  g_h2[N_NODES * C_OUT];
__device__ float  g_f2s[N_NODES];
__device__ float  g_f2d[N_NODES];

// ---------------------------------------------------------------------------
// CSR build, one warp per row (R12 kernel).
// ---------------------------------------------------------------------------
__device__ __forceinline__ unsigned nib_ne0(unsigned w) {
    return (((__vcmpne4(w, 0u) & 0x01010101u) * 0x01020408u) >> 24) & 0xFu;
}

__global__ __launch_bounds__(256) void build_csr(const void* adjv) {
    int warp = (blockIdx.x * blockDim.x + threadIdx.x) >> 5;
    int lane = threadIdx.x & 31;
    if (warp >= N_NODES) return;
    int row = warp;

    const unsigned char* a8 = (const unsigned char*)adjv;
    bool byte_mode = ((a8[8193] | a8[3 * 8193] | a8[5 * 8193]) != 0);

    int cnt = 0;
    int* nbr = g_nbr + (size_t)row * MAXDEG;

    if (!byte_mode) {
        const uint4* p = (const uint4*)((const unsigned*)adjv + (size_t)row * N_NODES);
        #pragma unroll
        for (int j = 0; j < 16; j++)
            asm volatile("prefetch.global.L2 [%0];" :: "l"(p + j * 32 + lane));
        #pragma unroll 1
        for (int it = 0; it < 64; it += 8) {
            if (it + 16 < 64) {
                #pragma unroll
                for (int j = 0; j < 8; j++)
                    asm volatile("prefetch.global.L2 [%0];"
                                 :: "l"(p + (it + 16 + j) * 32 + lane));
            }
            uint4 v[8];
            #pragma unroll
            for (int j = 0; j < 8; j++) v[j] = p[(it + j) * 32 + lane];
            unsigned mask = 0;
            #pragma unroll
            for (int j = 0; j < 8; j++) {
                mask |= (v[j].x != 0u ? 1u : 0u) << (j * 4);
                mask |= (v[j].y != 0u ? 2u : 0u) << (j * 4);
                mask |= (v[j].z != 0u ? 4u : 0u) << (j * 4);
                mask |= (v[j].w != 0u ? 8u : 0u) << (j * 4);
            }
            int myc = __popc(mask);
            int scan = myc;
            #pragma unroll
            for (int o = 1; o < 32; o <<= 1) {
                int t = __shfl_up_sync(0xFFFFFFFFu, scan, o);
                if (lane >= o) scan += t;
            }
            int pos = cnt + scan - myc;
            while (mask) {
                int b = __ffs(mask) - 1;
                mask &= mask - 1;
                int col = ((it + (b >> 2)) * 32 + lane) * 4 + (b & 3);
                if (pos < MAXDEG) nbr[pos] = col;
                pos++;
            }
            cnt += __shfl_sync(0xFFFFFFFFu, scan, 31);
        }
    } else {
        const uint4* p = (const uint4*)(a8 + (size_t)row * N_NODES);
        #pragma unroll 1
        for (int it = 0; it < 16; it += 4) {
            uint4 v[4];
            #pragma unroll
            for (int j = 0; j < 4; j++) v[j] = p[(it + j) * 32 + lane];
            #pragma unroll
            for (int j = 0; j < 4; j++) {
                unsigned mask = nib_ne0(v[j].x) | (nib_ne0(v[j].y) << 4)
                              | (nib_ne0(v[j].z) << 8) | (nib_ne0(v[j].w) << 12);
                int myc = __popc(mask);
                int scan = myc;
                #pragma unroll
                for (int o = 1; o < 32; o <<= 1) {
                    int t = __shfl_up_sync(0xFFFFFFFFu, scan, o);
                    if (lane >= o) scan += t;
                }
                int pos = cnt + scan - myc;
                int colbase = ((it + j) * 32 + lane) * 16;
                while (mask) {
                    int b = __ffs(mask) - 1;
                    mask &= mask - 1;
                    if (pos < MAXDEG) nbr[pos] = colbase + b;
                    pos++;
                }
                cnt += __shfl_sync(0xFFFFFFFFu, scan, 31);
            }
        }
    }
    if (lane == 0) g_deg[row] = (cnt < MAXDEG) ? cnt : MAXDEG;
}

// ---------------------------------------------------------------------------
// GEMM1 on tensor cores, 2-term tf32 split (A hi only; B hi+lo),
// double-buffered, fused f1s/f1d epilogue, fp16 Hall store.
// ---------------------------------------------------------------------------
#define BM 64
#define BK 16

#define OFF_AHI 0          // [2][64][20]  = 2560
#define OFF_BHI 2560       // [2][16][136] = 4352
#define OFF_BLO 6912
#define OFF_SHS 11264
#define OFF_SHD 11328
#define SMEM_WORDS 11392   // 45568 bytes

#define A_HI(b, r, c) sm[OFF_AHI + (b) * 1280 + (r) * 20 + (c)]
#define B_HI(b, k, n) sm[OFF_BHI + (b) * 2176 + (k) * 136 + (n)]
#define B_LO(b, k, n) sm[OFF_BLO + (b) * 2176 + (k) * 136 + (n)]

__device__ __forceinline__ void split_tf32(float v, unsigned& hi, unsigned& lo) {
    asm("cvt.rna.tf32.f32 %0, %1;" : "=r"(hi) : "f"(v));
    float r = v - __uint_as_float(hi);
    asm("cvt.rna.tf32.f32 %0, %1;" : "=r"(lo) : "f"(r));
}

__device__ __forceinline__ unsigned to_tf32(float v) {
    unsigned r;
    asm("cvt.rna.tf32.f32 %0, %1;" : "=r"(r) : "f"(v));
    return r;
}

#define MMA_TF32(c, a0, a1, a2, a3, b0, b1)                                     \
    asm volatile(                                                               \
        "mma.sync.aligned.m16n8k8.row.col.f32.tf32.tf32.f32 "                   \
        "{%0,%1,%2,%3},{%4,%5,%6,%7},{%8,%9},{%0,%1,%2,%3};"                    \
        : "+f"(c[0]), "+f"(c[1]), "+f"(c[2]), "+f"(c[3])                        \
        : "r"(a0), "r"(a1), "r"(a2), "r"(a3), "r"(b0), "r"(b1))

__global__ __launch_bounds__(256, 2) void gemm1_tc(const float* __restrict__ x,
                                                   const float* __restrict__ W1,
                                                   const float* __restrict__ a1s,
                                                   const float* __restrict__ a1d) {
    extern __shared__ unsigned sm[];
    float* sh_s = (float*)(sm + OFF_SHS);
    float* sh_d = (float*)(sm + OFF_SHD);

    const int head = blockIdx.x;
    const int row0 = blockIdx.y * BM;
    const int tid  = threadIdx.x;
    const int warp = tid >> 5;
    const int lane = tid & 31;
    const int warpM = warp >> 2;
    const int warpN = warp & 3;
    const float* Wh = W1 + (size_t)head * F_IN * H1;

    if (tid < BM) { sh_s[tid] = 0.0f; sh_d[tid] = 0.0f; }

    float acc[2][4][4];
    #pragma unroll
    for (int mt = 0; mt < 2; mt++)
        #pragma unroll
        for (int nt = 0; nt < 4; nt++)
            #pragma unroll
            for (int r = 0; r < 4; r++) acc[mt][nt][r] = 0.0f;

    const int aM  = tid >> 2;
    const int aK4 = (tid & 3) * 4;
    const int bK[2]  = { (0 * 256 + tid) >> 5,       (1 * 256 + tid) >> 5 };
    const int bN4[2] = { ((0 * 256 + tid) & 31) * 4, ((1 * 256 + tid) & 31) * 4 };

    float4 ax, bw[2];

    ax = *(const float4*)(x + (size_t)(row0 + aM) * F_IN + aK4);
    #pragma unroll
    for (int it = 0; it < 2; it++)
        bw[it] = *(const float4*)(Wh + (size_t)bK[it] * H1 + bN4[it]);
    {
        uint4 h4, l4;
        h4.x = to_tf32(ax.x); h4.y = to_tf32(ax.y);
        h4.z = to_tf32(ax.z); h4.w = to_tf32(ax.w);
        *(uint4*)&A_HI(0, aM, aK4) = h4;
        #pragma unroll
        for (int it = 0; it < 2; it++) {
            split_tf32(bw[it].x, h4.x, l4.x);
            split_tf32(bw[it].y, h4.y, l4.y);
            split_tf32(bw[it].z, h4.z, l4.z);
            split_tf32(bw[it].w, h4.w, l4.w);
            *(uint4*)&B_HI(0, bK[it], bN4[it]) = h4;
            *(uint4*)&B_LO(0, bK[it], bN4[it]) = l4;
        }
    }
    __syncthreads();

    const int NT = F_IN / BK;
    for (int i = 0; i < NT; i++) {
        const int cur = i & 1;
        const bool has_next = (i + 1 < NT);
        if (has_next) {
            const int kn = (i + 1) * BK;
            ax = *(const float4*)(x + (size_t)(row0 + aM) * F_IN + kn + aK4);
            #pragma unroll
            for (int it = 0; it < 2; it++)
                bw[it] = *(const float4*)(Wh + (size_t)(kn + bK[it]) * H1 + bN4[it]);
        }

        #pragma unroll
        for (int ks = 0; ks < 2; ks++) {
            const int kb = ks * 8;
            unsigned ah[2][4], bh[4][2], bl[4][2];
            const int ar = warpM * 32 + (lane >> 2);
            const int kc = kb + (lane & 3);
            #pragma unroll
            for (int mt = 0; mt < 2; mt++) {
                int r = ar + mt * 16;
                ah[mt][0] = A_HI(cur, r, kc);     ah[mt][1] = A_HI(cur, r + 8, kc);
                ah[mt][2] = A_HI(cur, r, kc + 4); ah[mt][3] = A_HI(cur, r + 8, kc + 4);
            }
            const int bn = warpN * 32 + (lane >> 2);
            const int kr = kb + (lane & 3);
            #pragma unroll
            for (int nt = 0; nt < 4; nt++) {
                bh[nt][0] = B_HI(cur, kr, bn + nt * 8);
                bh[nt][1] = B_HI(cur, kr + 4, bn + nt * 8);
                bl[nt][0] = B_LO(cur, kr, bn + nt * 8);
                bl[nt][1] = B_LO(cur, kr + 4, bn + nt * 8);
            }
            #pragma unroll
            for (int mt = 0; mt < 2; mt++)
                #pragma unroll
                for (int nt = 0; nt < 4; nt++) {
                    MMA_TF32(acc[mt][nt], ah[mt][0], ah[mt][1], ah[mt][2], ah[mt][3],
                             bh[nt][0], bh[nt][1]);
                    MMA_TF32(acc[mt][nt], ah[mt][0], ah[mt][1], ah[mt][2], ah[mt][3],
                             bl[nt][0], bl[nt][1]);
                }
        }

        if (has_next) {
            const int nxt = cur ^ 1;
            uint4 h4, l4;
            h4.x = to_tf32(ax.x); h4.y = to_tf32(ax.y);
            h4.z = to_tf32(ax.z); h4.w = to_tf32(ax.w);
            *(uint4*)&A_HI(nxt, aM, aK4) = h4;
            #pragma unroll
            for (int it = 0; it < 2; it++) {
                split_tf32(bw[it].x, h4.x, l4.x);
                split_tf32(bw[it].y, h4.y, l4.y);
                split_tf32(bw[it].z, h4.z, l4.z);
                split_tf32(bw[it].w, h4.w, l4.w);
                *(uint4*)&B_HI(nxt, bK[it], bN4[it]) = h4;
                *(uint4*)&B_LO(nxt, bK[it], bN4[it]) = l4;
            }
            __syncthreads();
        }
    }

    float asv[4][2], adv[4][2];
    const int colb = warpN * 32;
    #pragma unroll
    for (int nt = 0; nt < 4; nt++) {
        int c = colb + nt * 8 + 2 * (lane & 3);
        asv[nt][0] = a1s[head * H1 + c];
        asv[nt][1] = a1s[head * H1 + c + 1];
        adv[nt][0] = a1d[head * H1 + c];
        adv[nt][1] = a1d[head * H1 + c + 1];
    }

    __syncthreads();
    #pragma unroll
    for (int mt = 0; mt < 2; mt++) {
        float s0 = 0.f, s1 = 0.f, d0 = 0.f, d1 = 0.f;
        #pragma unroll
        for (int nt = 0; nt < 4; nt++) {
            s0 += acc[mt][nt][0] * asv[nt][0] + acc[mt][nt][1] * asv[nt][1];
            s1 += acc[mt][nt][2] * asv[nt][0] + acc[mt][nt][3] * asv[nt][1];
            d0 += acc[mt][nt][0] * adv[nt][0] + acc[mt][nt][1] * adv[nt][1];
            d1 += acc[mt][nt][2] * adv[nt][0] + acc[mt][nt][3] * adv[nt][1];
        }
        #pragma unroll
        for (int o = 1; o <= 2; o <<= 1) {
            s0 += __shfl_xor_sync(0xFFFFFFFFu, s0, o);
            s1 += __shfl_xor_sync(0xFFFFFFFFu, s1, o);
            d0 += __shfl_xor_sync(0xFFFFFFFFu, d0, o);
            d1 += __shfl_xor_sync(0xFFFFFFFFu, d1, o);
        }
        int rl = warpM * 32 + mt * 16 + (lane >> 2);
        if ((lane & 3) == 0) {
            atomicAdd(&sh_s[rl], s0);     atomicAdd(&sh_d[rl], d0);
            atomicAdd(&sh_s[rl + 8], s1); atomicAdd(&sh_d[rl + 8], d1);
        }
        int gr0 = row0 + rl;
        #pragma unroll
        for (int nt = 0; nt < 4; nt++) {
            int c = head * H1 + colb + nt * 8 + 2 * (lane & 3);
            *(__half2*)&g_Hall[(size_t)gr0 * HCAT + c] =
                __floats2half2_rn(acc[mt][nt][0], acc[mt][nt][1]);
            *(__half2*)&g_Hall[(size_t)(gr0 + 8) * HCAT + c] =
                __floats2half2_rn(acc[mt][nt][2], acc[mt][nt][3]);
        }
    }
    __syncthreads();
    if (tid < BM) {
        g_f1s[head][row0 + tid] = sh_s[tid];
        g_f1d[head][row0 + tid] = sh_d[tid];
    }
}

// ---------------------------------------------------------------------------
// Layer-1 attention + aggregate (fp16 gathers) + relu, fused layer-2 GEMM.
// ---------------------------------------------------------------------------
__global__ __launch_bounds__(256) void attn1_fused(const float* __restrict__ W2,
                                                   const float* __restrict__ a2s,
                                                   const float* __restrict__ a2d) {
    const int n = blockIdx.x;
    __shared__ int    s_nbr[MAXDEG];
    __shared__ float  s_w[2][MAXDEG];
    __shared__ float  s_red[2][2];
    __shared__ float4 s_acc[3][64];
    __shared__ float  s_h1[HCAT];
    __shared__ float  s_p[16][17];
    const int tid = threadIdx.x;
    const int deg = g_deg[n];

    if (tid < deg) s_nbr[tid] = g_nbr[(size_t)n * MAXDEG + tid];
    __syncthreads();
    if (tid < deg) {
        int m = s_nbr[tid];
        #pragma unroll
        for (int k = 0; k < 2; k++) {
            float e = g_f1s[k][n] + g_f1d[k][m];
            s_w[k][tid] = (e > 0.0f) ? e : LALPHA * e;
        }
    }
    __syncthreads();
    {
        int w = tid >> 5, lane = tid & 31;
        if (w < 2) {
            float mx = -1e30f;
            for (int i = lane; i < deg; i += 32) mx = fmaxf(mx, s_w[w][i]);
            #pragma unroll
            for (int o = 16; o; o >>= 1) mx = fmaxf(mx, __shfl_xor_sync(0xFFFFFFFFu, mx, o));
            float sm = 0.0f;
            for (int i = lane; i < deg; i += 32) sm += __expf(s_w[w][i] - mx);
            #pragma unroll
            for (int o = 16; o; o >>= 1) sm += __shfl_xor_sync(0xFFFFFFFFu, sm, o);
            if (lane == 0) { s_red[w][0] = mx; s_red[w][1] = sm; }
        }
    }
    __syncthreads();
    if (tid < deg) {
        #pragma unroll
        for (int k = 0; k < 2; k++)
            s_w[k][tid] = __expf(s_w[k][tid] - s_red[k][0]) / s_red[k][1];
    }
    __syncthreads();

    const int g  = tid >> 6;
    const int c4 = tid & 63;
    const int k  = c4 >> 5;
    float4 acc = make_float4(0.f, 0.f, 0.f, 0.f);
    for (int i = g; i < deg; i += 4) {
        float w = s_w[k][i];
        uint2 raw = *(const uint2*)&g_Hall[(size_t)s_nbr[i] * HCAT + 4 * c4];
        float2 f01 = __half22float2(*(__half2*)&raw.x);
        float2 f23 = __half22float2(*(__half2*)&raw.y);
        acc.x = fmaf(w, f01.x, acc.x);
        acc.y = fmaf(w, f01.y, acc.y);
        acc.z = fmaf(w, f23.x, acc.z);
        acc.w = fmaf(w, f23.y, acc.w);
    }
    if (g) s_acc[g - 1][c4] = acc;
    __syncthreads();
    if (g == 0) {
        #pragma unroll
        for (int j = 0; j < 3; j++) {
            float4 v = s_acc[j][c4];
            acc.x += v.x; acc.y += v.y; acc.z += v.z; acc.w += v.w;
        }
        acc.x = fmaxf(acc.x, 0.f); acc.y = fmaxf(acc.y, 0.f);
        acc.z = fmaxf(acc.z, 0.f); acc.w = fmaxf(acc.w, 0.f);
        *(float4*)&s_h1[4 * c4] = acc;
    }
    __syncthreads();

    const int fg = tid >> 4;
    const int c  = tid & 15;
    float pa = 0.0f;
    #pragma unroll
    for (int j = 0; j < 16; j++) {
        int f = fg * 16 + j;
        pa = fmaf(s_h1[f], W2[f * C_OUT + c], pa);
    }
    s_p[fg][c] = pa;
    __syncthreads();
    if (tid < 16) {
        float h2c = 0.0f;
        #pragma unroll
        for (int j = 0; j < 16; j++) h2c += s_p[j][tid];
        g_h2[n * C_OUT + tid] = h2c;
        float vs = h2c * a2s[tid];
        float vd = h2c * a2d[tid];
        #pragma unroll
        for (int o = 8; o; o >>= 1) {
            vs += __shfl_xor_sync(0x0000FFFFu, vs, o, 16);
            vd += __shfl_xor_sync(0x0000FFFFu, vd, o, 16);
        }
        if (tid == 0) { g_f2s[n] = vs; g_f2d[n] = vd; }
    }
}

// ---------------------------------------------------------------------------
// Layer-2 attention: one warp per node, neighbor-per-lane.
// ---------------------------------------------------------------------------
__global__ __launch_bounds__(256) void attn2(float* __restrict__ out) {
    int wIn = threadIdx.x >> 5, lane = threadIdx.x & 31;
    int n = blockIdx.x * 8 + wIn;
    if (n >= N_NODES) return;
    int deg = g_deg[n];
    const int* nbr = g_nbr + (size_t)n * MAXDEG;
    float fsn = g_f2s[n];

    int   myn[4];
    float ev[4];
    int cnt = 0;
    float mx = -1e30f;
    for (int i = lane; i < deg; i += 32) {
        int m = nbr[i];
        float e = fsn + g_f2d[m];
        e = (e > 0.0f) ? e : LALPHA * e;
        if (cnt < 4) { myn[cnt] = m; ev[cnt] = e; cnt++; }
        mx = fmaxf(mx, e);
    }
    #pragma unroll
    for (int o = 16; o; o >>= 1) mx = fmaxf(mx, __shfl_xor_sync(0xFFFFFFFFu, mx, o));
    float sm = 0.0f;
    #pragma unroll
    for (int j = 0; j < 4; j++)
        if (j < cnt) { ev[j] = __expf(ev[j] - mx); sm += ev[j]; }
    #pragma unroll
    for (int o = 16; o; o >>= 1) sm += __shfl_xor_sync(0xFFFFFFFFu, sm, o);
    float inv = 1.0f / sm;

    float4 a0 = make_float4(0,0,0,0), a1 = make_float4(0,0,0,0);
    float4 a2 = make_float4(0,0,0,0), a3 = make_float4(0,0,0,0);
    #pragma unroll
    for (int j = 0; j < 4; j++) {
        if (j < cnt) {
            float w = ev[j];
            const float4* hp = (const float4*)&g_h2[(size_t)myn[j] * C_OUT];
            float4 v0 = hp[0], v1 = hp[1], v2 = hp[2], v3 = hp[3];
            a0.x = fmaf(w, v0.x, a0.x); a0.y = fmaf(w, v0.y, a0.y);
            a0.z = fmaf(w, v0.z, a0.z); a0.w = fmaf(w, v0.w, a0.w);
            a1.x = fmaf(w, v1.x, a1.x); a1.y = fmaf(w, v1.y, a1.y);
            a1.z = fmaf(w, v1.z, a1.z); a1.w = fmaf(w, v1.w, a1.w);
            a2.x = fmaf(w, v2.x, a2.x); a2.y = fmaf(w, v2.y, a2.y);
            a2.z = fmaf(w, v2.z, a2.z); a2.w = fmaf(w, v2.w, a2.w);
            a3.x = fmaf(w, v3.x, a3.x); a3.y = fmaf(w, v3.y, a3.y);
            a3.z = fmaf(w, v3.z, a3.z); a3.w = fmaf(w, v3.w, a3.w);
        }
    }
    #pragma unroll
    for (int o = 16; o; o >>= 1) {
        a0.x += __shfl_xor_sync(0xFFFFFFFFu, a0.x, o);
        a0.y += __shfl_xor_sync(0xFFFFFFFFu, a0.y, o);
        a0.z += __shfl_xor_sync(0xFFFFFFFFu, a0.z, o);
        a0.w += __shfl_xor_sync(0xFFFFFFFFu, a0.w, o);
        a1.x += __shfl_xor_sync(0xFFFFFFFFu, a1.x, o);
        a1.y += __shfl_xor_sync(0xFFFFFFFFu, a1.y, o);
        a1.z += __shfl_xor_sync(0xFFFFFFFFu, a1.z, o);
        a1.w += __shfl_xor_sync(0xFFFFFFFFu, a1.w, o);
        a2.x += __shfl_xor_sync(0xFFFFFFFFu, a2.x, o);
        a2.y += __shfl_xor_sync(0xFFFFFFFFu, a2.y, o);
        a2.z += __shfl_xor_sync(0xFFFFFFFFu, a2.z, o);
        a2.w += __shfl_xor_sync(0xFFFFFFFFu, a2.w, o);
        a3.x += __shfl_xor_sync(0xFFFFFFFFu, a3.x, o);
        a3.y += __shfl_xor_sync(0xFFFFFFFFu, a3.y, o);
        a3.z += __shfl_xor_sync(0xFFFFFFFFu, a3.z, o);
        a3.w += __shfl_xor_sync(0xFFFFFFFFu, a3.w, o);
    }
    if (lane == 0) {
        float4* op = (float4*)&out[(size_t)n * C_OUT];
        a0.x *= inv; a0.y *= inv; a0.z *= inv; a0.w *= inv;
        a1.x *= inv; a1.y *= inv; a1.z *= inv; a1.w *= inv;
        a2.x *= inv; a2.y *= inv; a2.z *= inv; a2.w *= inv;
        a3.x *= inv; a3.y *= inv; a3.z *= inv; a3.w *= inv;
        op[0] = a0; op[1] = a1; op[2] = a2; op[3] = a3;
    }
}

// ---------------------------------------------------------------------------
extern "C" void kernel_launch(void* const* d_in, const int* in_sizes, int n_in,
                              void* d_out, int out_size) {
    const float* x   = (const float*)d_in[0];
    const void*  adj = d_in[1];
    const float* W1  = (const float*)d_in[2];
    const float* a1s = (const float*)d_in[3];
    const float* a1d = (const float*)d_in[4];
    const float* W2  = (const float*)d_in[5];
    const float* a2s = (const float*)d_in[6];
    const float* a2d = (const float*)d_in[7];
    float* out = (float*)d_out;

    static cudaStream_t s_side = nullptr;
    static cudaEvent_t  s_fork = nullptr, s_join = nullptr;
    static bool s_attr_done = false;
    if (!s_side) {
        cudaStreamCreateWithFlags(&s_side, cudaStreamNonBlocking);
        cudaEventCreateWithFlags(&s_fork, cudaEventDisableTiming);
        cudaEventCreateWithFlags(&s_join, cudaEventDisableTiming);
    }
    if (!s_attr_done) {
        cudaFuncSetAttribute(gemm1_tc, cudaFuncAttributeMaxDynamicSharedMemorySize,
                             SMEM_WORDS * 4);
        s_attr_done = true;
    }

    // fork: gemm on side stream (2 CTAs/SM), csr on main (R12 structure).
    cudaEventRecord(s_fork, 0);
    cudaStreamWaitEvent(s_side, s_fork, 0);

    dim3 g1(KHEADS, N_NODES / BM);             // (2, 128) = 256 CTAs
    gemm1_tc<<<g1, 256, SMEM_WORDS * 4, s_side>>>(x, W1, a1s, a1d);

    build_csr<<<N_NODES / 8, 256>>>(adj);

    cudaEventRecord(s_join, s_side);
    cudaStreamWaitEvent(0, s_join, 0);

    attn1_fused<<<N_NODES, 256>>>(W2, a2s, a2d);
    attn2<<<N_NODES / 8, 256>>>(out);
}